// round 16
// baseline (speedup 1.0000x reference)
#include <cuda_runtime.h>
#include <cuda_fp16.h>

// KNNInterpolate — L2-traffic-optimized pipeline with index-binned gather.
//
// Gather was at ~94% of the LTS chip cap (320 MB compulsory). R15 creates L1
// locality that LTS-bound random gathers lack: prep scatters query ids into
// 1024 bins by (i0 >> 6); gather runs one block per bin so each block's
// a-rows live in one 16 KB table segment (L1-resident, ~75% hits bypass L2).
// b/c rows stream through evict-first. Expected ~45 MB less LTS traffic.
//
// Inputs (metadata order):
//   d_in[0] s_feats          float32 [65536, 128]
//   d_in[1] q_points         float32 [262144, 3]
//   d_in[2] s_points         float32 [65536, 3]
//   d_in[3] neighbor_indices int32   [262144, 3]
// Output: float32 [262144, 128]

#define C_FEAT 128
#define N_SRC 65536
#define M_QRY 262144
#define EPS 1e-8f

// fp16 feature table: 16 MB, as uint4.
#define FEATS_U4 (N_SRC * C_FEAT / 8)   // 1048576
__device__ uint4 g_feats_h[FEATS_U4];

// 16B metadata: x=i0, y=i1, z=i2, w=half2(w0,w1). w2 = 1-w0-w1.
__device__ int4 g_meta[M_QRY];

// Binning: 1024 bins over i0>>6 (16 KB table segments). Poisson(256) counts;
// capacity 384 = +8 sigma, overflow probability ~0 for this fixed input.
#define NBINS 1024
#define BIN_CAP 384
__device__ int g_cnt[NBINS];
__device__ int g_perm[NBINS * BIN_CAP];

#define PREP_THREADS M_QRY
#define CONV_PER_THREAD (FEATS_U4 / PREP_THREADS)   // 4

__global__ __launch_bounds__(1024) void init_kernel()
{
    g_cnt[threadIdx.x] = 0;   // one block, 1024 threads
}

__device__ __forceinline__ float wgt3(const float* __restrict__ sp, int i,
                                      float qx, float qy, float qz)
{
    float dx = qx - __ldg(sp + 3ll * i + 0);
    float dy = qy - __ldg(sp + 3ll * i + 1);
    float dz = qz - __ldg(sp + 3ll * i + 2);
    return 1.0f / (dx * dx + dy * dy + dz * dz + EPS);
}

__device__ __forceinline__ unsigned pack_h2(float a, float b)
{
    __half2 h = __floats2half2_rn(a, b);
    return *reinterpret_cast<unsigned*>(&h);
}

// Single-wave fused prep: conversion burst + weights + binned scatter.
__global__ __launch_bounds__(256, 8) void prep_kernel(
    const float* __restrict__ s_feats,
    const float* __restrict__ q_points,
    const float* __restrict__ s_points,
    const int* __restrict__ nidx)
{
    const int t = blockIdx.x * 256 + threadIdx.x;   // 0..262143

    // ---- conversion: 4 independent coalesced 16B records (8 LDG.128) ----
    {
        const float4* src = (const float4*)s_feats;
        #pragma unroll
        for (int k = 0; k < CONV_PER_THREAD; k++) {
            const long long r = t + (long long)k * PREP_THREADS;
            const float4 f0 = __ldcs(src + 2 * r);
            const float4 f1 = __ldcs(src + 2 * r + 1);
            uint4 p;
            p.x = pack_h2(f0.x, f0.y);
            p.y = pack_h2(f0.z, f0.w);
            p.z = pack_h2(f1.x, f1.y);
            p.w = pack_h2(f1.z, f1.w);
            g_feats_h[r] = p;
        }
    }

    // ---- weights + binned scatter: one query per thread ----
    {
        const int m = t;
        const int i0 = __ldg(nidx + 3ll * m + 0);
        const int i1 = __ldg(nidx + 3ll * m + 1);
        const int i2 = __ldg(nidx + 3ll * m + 2);

        const float qx = __ldg(q_points + 3ll * m + 0);
        const float qy = __ldg(q_points + 3ll * m + 1);
        const float qz = __ldg(q_points + 3ll * m + 2);

        float w0 = wgt3(s_points, i0, qx, qy, qz);
        float w1 = wgt3(s_points, i1, qx, qy, qz);
        float w2 = wgt3(s_points, i2, qx, qy, qz);
        const float s = 1.0f / (w0 + w1 + w2);

        int4 mv;
        mv.x = i0;
        mv.y = i1;
        mv.z = i2;
        mv.w = (int)pack_h2(w0 * s, w1 * s);
        g_meta[m] = mv;

        const int bin = i0 >> 6;                      // 1024 bins
        const int pos = atomicAdd(&g_cnt[bin], 1);
        g_perm[bin * BIN_CAP + pos] = m;
    }
}

// Weighted sum of three fp16 4-channel chunks (fp32 accumulate).
__device__ __forceinline__ float4 wsum_h(uint2 ga, uint2 gb, uint2 gc,
                                         float w0, float w1, float w2)
{
    const float2 a01 = __half22float2(*reinterpret_cast<__half2*>(&ga.x));
    const float2 a23 = __half22float2(*reinterpret_cast<__half2*>(&ga.y));
    const float2 b01 = __half22float2(*reinterpret_cast<__half2*>(&gb.x));
    const float2 b23 = __half22float2(*reinterpret_cast<__half2*>(&gb.y));
    const float2 c01 = __half22float2(*reinterpret_cast<__half2*>(&gc.x));
    const float2 c23 = __half22float2(*reinterpret_cast<__half2*>(&gc.y));
    float4 r;
    r.x = w0 * a01.x; r.y = w0 * a01.y; r.z = w0 * a23.x; r.w = w0 * a23.y;
    r.x = fmaf(w1, b01.x, r.x); r.y = fmaf(w1, b01.y, r.y);
    r.z = fmaf(w1, b23.x, r.z); r.w = fmaf(w1, b23.y, r.w);
    r.x = fmaf(w2, c01.x, r.x); r.y = fmaf(w2, c01.y, r.y);
    r.z = fmaf(w2, c23.x, r.z); r.w = fmaf(w2, c23.y, r.w);
    return r;
}

// Process one query: a-row via L1-cached load (segment-local), b/c streamed.
__device__ __forceinline__ void do_query(int m, int lane, float4* __restrict__ out)
{
    const int4 mv = __ldcs(&g_meta[m]);
    unsigned pw = (unsigned)mv.w;
    const float2 w01 = __half22float2(*reinterpret_cast<__half2*>(&pw));
    const float w2 = 1.0f - w01.x - w01.y;

    const uint2* sfl = (const uint2*)g_feats_h + lane;
    const uint2 a = __ldg(sfl + 32ll * mv.x);    // L1-resident segment
    const uint2 b = __ldcs(sfl + 32ll * mv.y);   // stream, evict-first
    const uint2 c = __ldcs(sfl + 32ll * mv.z);

    __stcs(out + (long long)m * (C_FEAT / 4) + lane, wsum_h(a, b, c, w01.x, w01.y, w2));
}

// One block per bin; warps loop over the bin's queries in pairs.
__global__ __launch_bounds__(256) void gather_kernel(float4* __restrict__ out)
{
    const int bin = blockIdx.x;
    const int wid = threadIdx.x >> 5;
    const int lane = threadIdx.x & 31;
    const int n = g_cnt[bin];
    const int* __restrict__ pbase = g_perm + bin * BIN_CAP;

    for (int s = 2 * wid; s < n; s += 16) {
        const int m0 = __ldg(pbase + s);
        do_query(m0, lane, out);
        if (s + 1 < n) {
            const int m1 = __ldg(pbase + s + 1);
            do_query(m1, lane, out);
        }
    }
}

extern "C" void kernel_launch(void* const* d_in, const int* in_sizes, int n_in,
                              void* d_out, int out_size)
{
    const float* s_feats = (const float*)d_in[0];
    const float* q_points = (const float*)d_in[1];
    const float* s_points = (const float*)d_in[2];
    const int* nidx = (const int*)d_in[3];
    float4* out = (float4*)d_out;

    init_kernel<<<1, 1024>>>();
    prep_kernel<<<PREP_THREADS / 256, 256>>>(s_feats, q_points, s_points, nidx);
    gather_kernel<<<NBINS, 256>>>(out);
}

// round 17
// speedup vs baseline: 1.6215x; 1.6215x over previous
#include <cuda_runtime.h>
#include <cuda_fp16.h>

// KNNInterpolate — L2-traffic-optimized 2-kernel pipeline (R14 structure,
// reverted from the failed R15 binning experiment).
//
// Gather pass: ~90-94% of the LTS chip cap with compulsory traffic
// (192 MB fp16 gathers + 128 MB fp32 stores + 4 MB meta) — floored.
// Prep: single wave, each thread converts 4 full-MLP records then computes
// 1 query's weights. R16 tweak: the weights role's scattered loads (nidx,
// q_points) are issued BEFORE the conversion burst so their L2 latency
// overlaps the DRAM stream.
//
// Inputs (metadata order):
//   d_in[0] s_feats          float32 [65536, 128]
//   d_in[1] q_points         float32 [262144, 3]
//   d_in[2] s_points         float32 [65536, 3]
//   d_in[3] neighbor_indices int32   [262144, 3]
// Output: float32 [262144, 128]

#define C_FEAT 128
#define N_SRC 65536
#define M_QRY 262144
#define EPS 1e-8f

// fp16 feature table: 16 MB, as uint4.
#define FEATS_U4 (N_SRC * C_FEAT / 8)   // 1048576
__device__ uint4 g_feats_h[FEATS_U4];

// 16B metadata: x=i0, y=i1, z=i2, w=half2(w0,w1). w2 = 1-w0-w1.
__device__ int4 g_meta[M_QRY];

#define PREP_THREADS M_QRY                          // 1024 blocks x 256
#define CONV_PER_THREAD (FEATS_U4 / PREP_THREADS)   // 4

__device__ __forceinline__ unsigned pack_h2(float a, float b)
{
    __half2 h = __floats2half2_rn(a, b);
    return *reinterpret_cast<unsigned*>(&h);
}

// Single-wave fused prep.
__global__ __launch_bounds__(256, 6) void prep_kernel(
    const float* __restrict__ s_feats,
    const float* __restrict__ q_points,
    const float* __restrict__ s_points,
    const int* __restrict__ nidx)
{
    const int t = blockIdx.x * 256 + threadIdx.x;   // 0..262143
    const int m = t;                                 // this thread's query

    // ---- issue the weights role's scattered loads FIRST (long latency,
    //      overlapped by the conversion burst below) ----
    const int i0 = __ldg(nidx + 3ll * m + 0);
    const int i1 = __ldg(nidx + 3ll * m + 1);
    const int i2 = __ldg(nidx + 3ll * m + 2);
    const float qx = __ldg(q_points + 3ll * m + 0);
    const float qy = __ldg(q_points + 3ll * m + 1);
    const float qz = __ldg(q_points + 3ll * m + 2);

    // ---- conversion: 4 independent coalesced 16B records (8 LDG.128) ----
    {
        const float4* src = (const float4*)s_feats;
        #pragma unroll
        for (int k = 0; k < CONV_PER_THREAD; k++) {
            const long long r = t + (long long)k * PREP_THREADS;
            const float4 f0 = __ldcs(src + 2 * r);   // read-once
            const float4 f1 = __ldcs(src + 2 * r + 1);
            uint4 p;
            p.x = pack_h2(f0.x, f0.y);
            p.y = pack_h2(f0.z, f0.w);
            p.z = pack_h2(f1.x, f1.y);
            p.w = pack_h2(f1.z, f1.w);
            g_feats_h[r] = p;                        // stays in L2
        }
    }

    // ---- weights: point gathers (indices long since arrived) + math ----
    {
        float dx0 = qx - __ldg(s_points + 3ll * i0 + 0);
        float dy0 = qy - __ldg(s_points + 3ll * i0 + 1);
        float dz0 = qz - __ldg(s_points + 3ll * i0 + 2);
        float dx1 = qx - __ldg(s_points + 3ll * i1 + 0);
        float dy1 = qy - __ldg(s_points + 3ll * i1 + 1);
        float dz1 = qz - __ldg(s_points + 3ll * i1 + 2);
        float dx2 = qx - __ldg(s_points + 3ll * i2 + 0);
        float dy2 = qy - __ldg(s_points + 3ll * i2 + 1);
        float dz2 = qz - __ldg(s_points + 3ll * i2 + 2);

        float w0 = 1.0f / (dx0 * dx0 + dy0 * dy0 + dz0 * dz0 + EPS);
        float w1 = 1.0f / (dx1 * dx1 + dy1 * dy1 + dz1 * dz1 + EPS);
        float w2 = 1.0f / (dx2 * dx2 + dy2 * dy2 + dz2 * dz2 + EPS);
        const float s = 1.0f / (w0 + w1 + w2);

        int4 mv;
        mv.x = i0;
        mv.y = i1;
        mv.z = i2;
        mv.w = (int)pack_h2(w0 * s, w1 * s);
        g_meta[m] = mv;
    }
}

// Weighted sum of three fp16 4-channel chunks (fp32 accumulate).
__device__ __forceinline__ float4 wsum_h(uint2 ga, uint2 gb, uint2 gc,
                                         float w0, float w1, float w2)
{
    const float2 a01 = __half22float2(*reinterpret_cast<__half2*>(&ga.x));
    const float2 a23 = __half22float2(*reinterpret_cast<__half2*>(&ga.y));
    const float2 b01 = __half22float2(*reinterpret_cast<__half2*>(&gb.x));
    const float2 b23 = __half22float2(*reinterpret_cast<__half2*>(&gb.y));
    const float2 c01 = __half22float2(*reinterpret_cast<__half2*>(&gc.x));
    const float2 c23 = __half22float2(*reinterpret_cast<__half2*>(&gc.y));
    float4 r;
    r.x = w0 * a01.x; r.y = w0 * a01.y; r.z = w0 * a23.x; r.w = w0 * a23.y;
    r.x = fmaf(w1, b01.x, r.x); r.y = fmaf(w1, b01.y, r.y);
    r.z = fmaf(w1, b23.x, r.z); r.w = fmaf(w1, b23.y, r.w);
    r.x = fmaf(w2, c01.x, r.x); r.y = fmaf(w2, c01.y, r.y);
    r.z = fmaf(w2, c23.x, r.z); r.w = fmaf(w2, c23.y, r.w);
    return r;
}

// One warp per TWO queries; each lane owns 4 channels (8B fp16 per gather).
__global__ __launch_bounds__(256) void gather_kernel(
    float4* __restrict__ out,
    int n_pairs)
{
    const int pair = (int)((blockIdx.x * blockDim.x + threadIdx.x) >> 5);
    const int lane = threadIdx.x & 31;
    if (pair >= n_pairs) return;

    const int m0 = 2 * pair;

    // 16B meta per query, read-once -> evict-first
    const int4 mv0 = __ldcs(&g_meta[m0]);
    const int4 mv1 = __ldcs(&g_meta[m0 + 1]);

    unsigned pw0 = (unsigned)mv0.w;
    unsigned pw1 = (unsigned)mv1.w;
    const float2 w01a = __half22float2(*reinterpret_cast<__half2*>(&pw0));
    const float2 w01b = __half22float2(*reinterpret_cast<__half2*>(&pw1));
    const float w2a = 1.0f - w01a.x - w01a.y;
    const float w2b = 1.0f - w01b.x - w01b.y;

    // fp16 row = 32 uint2 (256B); lane's chunk = uint2 at [row*32 + lane]
    const uint2* sfl = (const uint2*)g_feats_h + lane;

    const uint2 a0 = __ldg(sfl + 32ll * mv0.x);
    const uint2 b0 = __ldg(sfl + 32ll * mv0.y);
    const uint2 c0 = __ldg(sfl + 32ll * mv0.z);
    const uint2 a1 = __ldg(sfl + 32ll * mv1.x);
    const uint2 b1 = __ldg(sfl + 32ll * mv1.y);
    const uint2 c1 = __ldg(sfl + 32ll * mv1.z);

    float4* o = out + (long long)m0 * (C_FEAT / 4) + lane;
    __stcs(o, wsum_h(a0, b0, c0, w01a.x, w01a.y, w2a));
    __stcs(o + (C_FEAT / 4), wsum_h(a1, b1, c1, w01b.x, w01b.y, w2b));
}

extern "C" void kernel_launch(void* const* d_in, const int* in_sizes, int n_in,
                              void* d_out, int out_size)
{
    const float* s_feats = (const float*)d_in[0];
    const float* q_points = (const float*)d_in[1];
    const float* s_points = (const float*)d_in[2];
    const int* nidx = (const int*)d_in[3];
    float4* out = (float4*)d_out;

    const int M = in_sizes[1] / 3;   // 262144
    const int n_pairs = M / 2;

    prep_kernel<<<PREP_THREADS / 256, 256>>>(s_feats, q_points, s_points, nidx);

    const int warps_per_block = 8;   // 256 threads
    const int blocks = (n_pairs + warps_per_block - 1) / warps_per_block;
    gather_kernel<<<blocks, warps_per_block * 32>>>(out, n_pairs);
}